// round 17
// baseline (speedup 1.0000x reference)
#include <cuda_runtime.h>
#include <cuda_bf16.h>
#include <cstdint>
#include <math.h>

#define B_  64
#define T_  1024
#define I_  512
#define H_  1024

// ===================== warp-mma helpers =====================================
__device__ __forceinline__ uint32_t smem_u32(const void* p) {
    uint32_t a;
    asm("{ .reg .u64 t; cvta.to.shared.u64 t, %1; cvt.u32.u64 %0, t; }"
        : "=r"(a) : "l"(p));
    return a;
}
__device__ __forceinline__ void ldsm4(uint32_t& r0, uint32_t& r1,
                                      uint32_t& r2, uint32_t& r3, uint32_t a) {
    asm volatile("ldmatrix.sync.aligned.m8n8.x4.shared.b16 {%0,%1,%2,%3}, [%4];"
                 : "=r"(r0), "=r"(r1), "=r"(r2), "=r"(r3) : "r"(a));
}
__device__ __forceinline__ void mma_bf16(float* c, const uint32_t* a,
                                         uint32_t b0, uint32_t b1) {
    asm volatile("mma.sync.aligned.m16n8k16.row.col.f32.bf16.bf16.f32 "
                 "{%0,%1,%2,%3}, {%4,%5,%6,%7}, {%8,%9}, {%0,%1,%2,%3};"
                 : "+f"(c[0]), "+f"(c[1]), "+f"(c[2]), "+f"(c[3])
                 : "r"(a[0]), "r"(a[1]), "r"(a[2]), "r"(a[3]),
                   "r"(b0), "r"(b1));
}
__device__ __forceinline__ void poll_ge(unsigned* p, unsigned tgt) {
    unsigned v;
    do { asm volatile("ld.acquire.gpu.global.u32 %0, [%1];"
                      : "=r"(v) : "l"(p)); } while (v < tgt);
}
__device__ __forceinline__ void rel_add1(unsigned* p) {
    asm volatile("red.release.gpu.global.add.u32 [%0], 1;" :: "l"(p) : "memory");
}
// split fp32 pair -> packed bf16x2 hi + lo
__device__ __forceinline__ void split2(float a, float b,
                                       uint32_t& h, uint32_t& l) {
    __nv_bfloat16 ha = __float2bfloat16_rn(a);
    __nv_bfloat16 hb = __float2bfloat16_rn(b);
    __nv_bfloat16 la = __float2bfloat16_rn(a - __bfloat162float(ha));
    __nv_bfloat16 lb = __float2bfloat16_rn(b - __bfloat162float(hb));
    __nv_bfloat162 hp; hp.x = ha; hp.y = hb;
    __nv_bfloat162 lp; lp.x = la; lp.y = lb;
    h = *(uint32_t*)&hp; l = *(uint32_t*)&lp;
}
// swizzled offset in a [.][64 k] bf16 tile (128 B rows)
__device__ __forceinline__ uint32_t tswz64c(int row, int chunk) {
    return (uint32_t)(row * 128) + (uint32_t)((chunk ^ (row & 7)) << 4);
}
// swizzled offset in a [.][1024 k] bf16 tile (2048 B rows)
__device__ __forceinline__ uint32_t tswz1k(int row, int k) {
    uint32_t kb = (uint32_t)(k * 2);
    return (uint32_t)(row * 2048) + ((((kb >> 4) ^ (row & 7)) << 4) | (kb & 15));
}

// ===================== global scratch =======================================
// h state as pre-swizzled bf16 tile images: [buf][hi/lo][mg][16 rows x 1024 k]
__device__ unsigned char g_hsp[2][2][4][32768];
__device__ unsigned g_prod[4];                       // per-mg step counters
__device__ __nv_bfloat16 g_iwt[2][H_ * I_];          // input_w^T hi/lo [n][k]

__global__ void init_kernel() {
    int idx = blockIdx.x * blockDim.x + threadIdx.x;   // 16384 threads
    ((uint4*)g_hsp[0])[idx] = make_uint4(0, 0, 0, 0);  // zero buf 0 (h0 = 0)
    if (idx < 4) g_prod[idx] = 0u;
}

// ===================== Phase 0: transpose + split input_w ===================
__global__ void __launch_bounds__(256)
convert_iw(const float* __restrict__ iw) {
    const int tid  = threadIdx.x;
    const int lane = tid & 31;
    const int gw   = blockIdx.x * 8 + (tid >> 5);   // 0..511
    const int n0   = (gw & 31) * 32;
    const int k0   = (gw >> 5) * 32;
    const int n    = n0 + lane;

    float w[32];
#pragma unroll
    for (int kr = 0; kr < 32; ++kr)
        w[kr] = iw[(size_t)(k0 + kr) * H_ + n];

    uint32_t hu[16], lu[16];
#pragma unroll
    for (int j = 0; j < 16; ++j)
        split2(w[2 * j], w[2 * j + 1], hu[j], lu[j]);

    char* dh = (char*)g_iwt[0] + (size_t)n * 1024 + k0 * 2;
    char* dl = (char*)g_iwt[1] + (size_t)n * 1024 + k0 * 2;
#pragma unroll
    for (int j = 0; j < 4; ++j) {
        *(uint4*)(dh + j * 16) = *(uint4*)&hu[j * 4];
        *(uint4*)(dl + j * 16) = *(uint4*)&lu[j * 4];
    }
}

// ===================== Phase 1: xp = x @ input_w + b (HMMA) =================
#define PJ_A_HI 0
#define PJ_A_LO 8192
#define PJ_W_HI 16384
#define PJ_W_LO 32768

__global__ void __launch_bounds__(256, 2)
proj_mma(const float* __restrict__ x, const float* __restrict__ bias,
         float* __restrict__ out) {
    __shared__ char smem[49152];
    const uint32_t sb = smem_u32(smem);
    const int tid  = threadIdx.x;
    const int wid  = tid >> 5;
    const int lane = tid & 31;
    const int n0g  = blockIdx.x * 128;
    const int m0g  = blockIdx.y * 64;

    const int m0w = (wid & 1) * 32;
    const int n0w = (wid >> 1) * 32;
    const int lr  = lane & 15;
    const int kh  = lane >> 4;

    const uint32_t a_hi0 = sb + PJ_A_HI + (uint32_t)((m0w + lr) * 128);
    const uint32_t a_hi1 = a_hi0 + 16 * 128;
    const uint32_t a_lo0 = sb + PJ_A_LO + (uint32_t)((m0w + lr) * 128);
    const uint32_t a_lo1 = a_lo0 + 16 * 128;
    const uint32_t w_hi0 = sb + PJ_W_HI + (uint32_t)((n0w + lr) * 128);
    const uint32_t w_hi1 = w_hi0 + 16 * 128;
    const uint32_t w_lo0 = sb + PJ_W_LO + (uint32_t)((n0w + lr) * 128);
    const uint32_t w_lo1 = w_lo0 + 16 * 128;

    float c[2][4][4];
#pragma unroll
    for (int i = 0; i < 2; ++i)
#pragma unroll
        for (int j = 0; j < 4; ++j)
            c[i][j][0] = c[i][j][1] = c[i][j][2] = c[i][j][3] = 0.f;

    const int arow = tid >> 2, akq = tid & 3;
    const int wrow = tid >> 1, whalf = tid & 1;

    for (int kt = 0; kt < 8; ++kt) {
        {
            const float* src = x + (size_t)(m0g + arow) * I_ + kt * 64 + akq * 16;
            float4 f0 = *(const float4*)(src + 0);
            float4 f1 = *(const float4*)(src + 4);
            float4 f2 = *(const float4*)(src + 8);
            float4 f3 = *(const float4*)(src + 12);
            uint32_t hu[8], lu[8];
            split2(f0.x, f0.y, hu[0], lu[0]); split2(f0.z, f0.w, hu[1], lu[1]);
            split2(f1.x, f1.y, hu[2], lu[2]); split2(f1.z, f1.w, hu[3], lu[3]);
            split2(f2.x, f2.y, hu[4], lu[4]); split2(f2.z, f2.w, hu[5], lu[5]);
            split2(f3.x, f3.y, hu[6], lu[6]); split2(f3.z, f3.w, hu[7], lu[7]);
#pragma unroll
            for (int c8 = 0; c8 < 2; ++c8) {
                uint32_t off = tswz64c(arow, akq * 2 + c8);
                *(uint4*)(smem + PJ_A_HI + off) = *(uint4*)&hu[c8 * 4];
                *(uint4*)(smem + PJ_A_LO + off) = *(uint4*)&lu[c8 * 4];
            }
        }
        {
            const char* sh = (const char*)g_iwt[0]
                           + (size_t)(n0g + wrow) * 1024 + kt * 128 + whalf * 64;
            const char* sl = (const char*)g_iwt[1]
                           + (size_t)(n0g + wrow) * 1024 + kt * 128 + whalf * 64;
#pragma unroll
            for (int j = 0; j < 4; ++j) {
                uint4 vh = __ldcg((const uint4*)(sh + j * 16));
                uint4 vl = __ldcg((const uint4*)(sl + j * 16));
                uint32_t off = tswz64c(wrow, whalf * 4 + j);
                *(uint4*)(smem + PJ_W_HI + off) = vh;
                *(uint4*)(smem + PJ_W_LO + off) = vl;
            }
        }
        __syncthreads();

#pragma unroll
        for (int s = 0; s < 4; ++s) {
            const uint32_t co = (uint32_t)(((2 * s + kh) ^ (lr & 7)) << 4);
            uint32_t ah[2][4], al[2][4], bh[4][2], bl[4][2];
            uint32_t x0, x1, x2, x3;
            ldsm4(ah[0][0], ah[0][1], ah[0][2], ah[0][3], a_hi0 + co);
            ldsm4(ah[1][0], ah[1][1], ah[1][2], ah[1][3], a_hi1 + co);
            ldsm4(al[0][0], al[0][1], al[0][2], al[0][3], a_lo0 + co);
            ldsm4(al[1][0], al[1][1], al[1][2], al[1][3], a_lo1 + co);
            ldsm4(x0, x1, x2, x3, w_hi0 + co);
            bh[0][0] = x0; bh[0][1] = x2; bh[1][0] = x1; bh[1][1] = x3;
            ldsm4(x0, x1, x2, x3, w_hi1 + co);
            bh[2][0] = x0; bh[2][1] = x2; bh[3][0] = x1; bh[3][1] = x3;
            ldsm4(x0, x1, x2, x3, w_lo0 + co);
            bl[0][0] = x0; bl[0][1] = x2; bl[1][0] = x1; bl[1][1] = x3;
            ldsm4(x0, x1, x2, x3, w_lo1 + co);
            bl[2][0] = x0; bl[2][1] = x2; bl[3][0] = x1; bl[3][1] = x3;
#pragma unroll
            for (int i = 0; i < 2; ++i)
#pragma unroll
                for (int j = 0; j < 4; ++j) {
                    mma_bf16(c[i][j], ah[i], bh[j][0], bh[j][1]);
                    mma_bf16(c[i][j], ah[i], bl[j][0], bl[j][1]);
                    mma_bf16(c[i][j], al[i], bh[j][0], bh[j][1]);
                }
        }
        __syncthreads();
    }

#pragma unroll
    for (int j = 0; j < 4; ++j) {
        const int col = n0g + n0w + j * 8 + 2 * (lane & 3);
        float2 bb = *(const float2*)(bias + col);
#pragma unroll
        for (int i = 0; i < 2; ++i) {
            const int r0 = m0g + m0w + i * 16 + (lane >> 2);
            *(float2*)(out + (size_t)r0 * H_ + col)
                = make_float2(c[i][j][0] + bb.x, c[i][j][1] + bb.y);
            *(float2*)(out + (size_t)(r0 + 8) * H_ + col)
                = make_float2(c[i][j][2] + bb.x, c[i][j][3] + bb.y);
        }
    }
}

// ===================== Phase 2: HMMA recurrence, warp-private A =============
// 128 CTAs = 4 m-groups x 32 n-groups. CTA: M=16 x N=32 x K=1024 split-bf16.
// K split 8 ways across warps; each warp's A slice (k-chunks [16w,16w+16)) is
// a CONTIGUOUS 256B-per-row block of the h image -> warp-private stage + poll,
// only TWO __syncthreads per step (pre-reduce, pre-arrive).
#define A_HI   0                    // 16 x 1024 bf16 = 32 KB
#define A_LO   32768
#define W_HI   65536                // 32 x 1024 bf16 = 64 KB
#define W_LO   131072
#define RED    196608               // 8 x 16 x 34 fp32
#define RSTR   34
#define RNN_SMEM_BYTES (196608 + 8 * 16 * RSTR * 4)

__global__ void __launch_bounds__(256, 1)
rnn_mma_kernel(const float* __restrict__ W, float* __restrict__ out) {
    extern __shared__ char smem[];
    const uint32_t sb = smem_u32(smem);
    float* red = (float*)(smem + RED);
    const int tid  = threadIdx.x;
    const int wid  = tid >> 5;
    const int lane = tid & 31;
    const int mg   = blockIdx.x >> 5;    // 0..3
    const int ng   = blockIdx.x & 31;    // 0..31
    const int nsl  = ng * 32;

    // ---- build W^T hi/lo tiles once: Wt[n][k] = W[k][nsl+n], swizzled ----
    for (int q = tid; q < 32 * 1024; q += 256) {
        int n = q & 31;
        int k = q >> 5;
        float w = W[(size_t)k * H_ + nsl + n];
        __nv_bfloat16 hi = __float2bfloat16_rn(w);
        __nv_bfloat16 lo = __float2bfloat16_rn(w - __bfloat162float(hi));
        uint32_t off = tswz1k(n, k);
        *(unsigned short*)(smem + W_HI + off) = *(unsigned short*)&hi;
        *(unsigned short*)(smem + W_LO + off) = *(unsigned short*)&lo;
    }
    __syncthreads();

    const int lr = lane & 15;
    const int kh = lane >> 4;

    const uint32_t a_hi = sb + A_HI + (uint32_t)(lr * 2048);
    const uint32_t a_lo = sb + A_LO + (uint32_t)(lr * 2048);
    const uint32_t w_h0 = sb + W_HI + (uint32_t)(lr * 2048);
    const uint32_t w_h1 = sb + W_HI + (uint32_t)((16 + lr) * 2048);
    const uint32_t w_l0 = sb + W_LO + (uint32_t)(lr * 2048);
    const uint32_t w_l1 = sb + W_LO + (uint32_t)((16 + lr) * 2048);
    const uint32_t swz = (uint32_t)(lane & 7);

    // warp-private A-slice copy addressing: warp w owns bytes
    // [row*2048 + w*256, +256) per row, for both hi and lo images.
    // Per lane: 8 uint4 (u = i*32+lane; row = u>>4; off16 = u&15).
    uint32_t aoff[8];
#pragma unroll
    for (int i = 0; i < 8; ++i) {
        int u = i * 32 + lane;
        aoff[i] = (uint32_t)((u >> 4) * 2048 + wid * 256 + (u & 15) * 16);
    }

    // epilogue assignment: 2 output elems (float2) per thread
    const int e   = tid * 2;
    const int rr  = e >> 5;              // 0..15 local row
    const int cc  = e & 31;              // even col in n-slice
    const int gr  = mg * 16 + rr;        // global batch row
    const uint32_t hoff = tswz1k(rr, nsl + cc);

    unsigned* ctr = &g_prod[mg];

    for (int t = 0; t < T_; ++t) {
        // ---- per-warp wait: producers of image mg finished step t-1 ----
        if (lane == 0) poll_ge(ctr, 32u * (unsigned)t);
        __syncwarp();

        // ---- prefetch xp (independent) ----
        size_t obase = ((size_t)gr * T_ + t) * H_ + nsl + cc;
        float2 xv = __ldcg((const float2*)(out + obase));

        // ---- warp-private stage: own 4KB hi + 4KB lo slice (MLP=16) ----
        const char* srcH = (const char*)g_hsp[t & 1][0][mg];
        const char* srcL = (const char*)g_hsp[t & 1][1][mg];
        uint4 vh[8], vl[8];
#pragma unroll
        for (int i = 0; i < 8; ++i) vh[i] = __ldcg((const uint4*)(srcH + aoff[i]));
#pragma unroll
        for (int i = 0; i < 8; ++i) vl[i] = __ldcg((const uint4*)(srcL + aoff[i]));
#pragma unroll
        for (int i = 0; i < 8; ++i) {
            *(uint4*)(smem + A_HI + aoff[i]) = vh[i];
            *(uint4*)(smem + A_LO + aoff[i]) = vl[i];
        }
        __syncwarp();                    // warp-private slice staged

        // ---- mma: warp's 128-k slice, 8 k16-steps, 3 split products ----
        float c[4][4];
#pragma unroll
        for (int j = 0; j < 4; ++j)
            c[j][0] = c[j][1] = c[j][2] = c[j][3] = 0.f;

#pragma unroll
        for (int s = 0; s < 8; ++s) {
            const uint32_t ch  = (uint32_t)(wid * 16 + 2 * s + kh);
            const uint32_t ca  = ((ch ^ swz) << 4);
            const uint32_t cw  = ((ch ^ (uint32_t)(lr & 7)) << 4);
            uint32_t ah[4], al[4];
            uint32_t x0, x1, x2, x3;
            ldsm4(ah[0], ah[1], ah[2], ah[3], a_hi + ca);
            ldsm4(al[0], al[1], al[2], al[3], a_lo + ca);
            ldsm4(x0, x1, x2, x3, w_h0 + cw);
            uint32_t bh0 = x0, bh1 = x2, bh0b = x1, bh1b = x3;
            ldsm4(x0, x1, x2, x3, w_h1 + cw);
            uint32_t bh2 = x0, bh3 = x2, bh2b = x1, bh3b = x3;
            ldsm4(x0, x1, x2, x3, w_l0 + cw);
            uint32_t bl0 = x0, bl1 = x2, bl0b = x1, bl1b = x3;
            ldsm4(x0, x1, x2, x3, w_l1 + cw);
            uint32_t bl2 = x0, bl3 = x2, bl2b = x1, bl3b = x3;

            mma_bf16(c[0], ah, bh0, bh1);
            mma_bf16(c[1], ah, bh0b, bh1b);
            mma_bf16(c[2], ah, bh2, bh3);
            mma_bf16(c[3], ah, bh2b, bh3b);
            mma_bf16(c[0], ah, bl0, bl1);
            mma_bf16(c[1], ah, bl0b, bl1b);
            mma_bf16(c[2], ah, bl2, bl3);
            mma_bf16(c[3], ah, bl2b, bl3b);
            mma_bf16(c[0], al, bh0, bh1);
            mma_bf16(c[1], al, bh0b, bh1b);
            mma_bf16(c[2], al, bh2, bh3);
            mma_bf16(c[3], al, bh2b, bh3b);
        }

        // ---- write this warp's partials (red aliases nothing) ----
        {
            const int r0 = lane >> 2;
            const int cb = 2 * (lane & 3);
#pragma unroll
            for (int j = 0; j < 4; ++j) {
                *(float2*)&red[(wid * 16 + r0) * RSTR + j * 8 + cb]
                    = make_float2(c[j][0], c[j][1]);
                *(float2*)&red[(wid * 16 + r0 + 8) * RSTR + j * 8 + cb]
                    = make_float2(c[j][2], c[j][3]);
            }
        }
        __syncthreads();                 // all partials written

        // ---- reduce 8 warps, add xp, tanh, write out + split-h image ----
        {
            float2 s2 = make_float2(0.f, 0.f);
#pragma unroll
            for (int w8 = 0; w8 < 8; ++w8) {
                float2 pv = *(const float2*)&red[(w8 * 16 + rr) * RSTR + cc];
                s2.x += pv.x; s2.y += pv.y;
            }
            float2 hn;
            hn.x = tanhf(s2.x + xv.x);
            hn.y = tanhf(s2.y + xv.y);
            __stcg((float2*)(out + obase), hn);

            uint32_t hp, lp;
            split2(hn.x, hn.y, hp, lp);
            const int nb = (t + 1) & 1;
            __stcg((unsigned int*)(g_hsp[nb][0][mg] + hoff), hp);
            __stcg((unsigned int*)(g_hsp[nb][1][mg] + hoff), lp);
        }
        __syncthreads();                 // epilogue stores + red reads done
        if (tid == 0) rel_add1(ctr);     // step t fully done
    }
}

// ===================== launch ===============================================
extern "C" void kernel_launch(void* const* d_in, const int* in_sizes, int n_in,
                              void* d_out, int out_size) {
    const float *x = nullptr, *hw = nullptr, *iw = nullptr, *bias = nullptr;
    for (int i = 0; i < n_in; ++i) {
        long long s = in_sizes[i];
        if      (s == (long long)B_ * T_ * I_) x    = (const float*)d_in[i];
        else if (s == (long long)H_ * H_)      hw   = (const float*)d_in[i];
        else if (s == (long long)I_ * H_)      iw   = (const float*)d_in[i];
        else if (s == (long long)H_)           bias = (const float*)d_in[i];
    }
    float* out = (float*)d_out;

    cudaFuncSetAttribute(rnn_mma_kernel,
                         cudaFuncAttributeMaxDynamicSharedMemorySize,
                         RNN_SMEM_BYTES);

    convert_iw<<<64, 256>>>(iw);
    proj_mma<<<dim3(8, 1024), 256>>>(x, bias, out);
    init_kernel<<<64, 256>>>();
    rnn_mma_kernel<<<128, 256, RNN_SMEM_BYTES>>>(hw, out);
}